// round 4
// baseline (speedup 1.0000x reference)
#include <cuda_runtime.h>
#include <cuda_bf16.h>

// BSplineNN: out[b,c] = sum_n coef[b,n,c] * B_{n,3}(x_b)
// B=4096, n=64, C=256, K=3, T=68.
// TWO warps per batch row (each warp: 128 channels, 4x LDG.128 per lane).
// Grid = 1024 blocks x 8 warps -> ~7 blocks/SM, occ ~80%.
// Critical-chain split: span j from ballots -> issue coef loads immediately
// -> compute divide-heavy weights while loads are in flight -> FMA -> store.

#define NB    4096
#define NCOEF 64
#define NCH   256
#define NT    68
#define WARPS_PER_BLOCK 8
#define ROWS_PER_BLOCK  4   // 2 warps per row

__device__ __forceinline__ float gdiv(float a, float d) {
    return (d == 0.0f) ? 0.0f : __fdividef(a, d);
}

__global__ __launch_bounds__(WARPS_PER_BLOCK * 32)
void bspline_kernel(const float* __restrict__ coef,   // [B, 64, 256]
                    const float* __restrict__ knots,  // [B, 68]
                    const float* __restrict__ inpce,  // [B, 1]
                    float* __restrict__ out)          // [B, 256]
{
    const int warp = threadIdx.x >> 5;
    const int lane = threadIdx.x & 31;
    const int b    = blockIdx.x * ROWS_PER_BLOCK + (warp >> 1);
    const int half = warp & 1;             // which 128-channel half

    const float* kt = knots + b * NT;
    const float  x  = __ldg(inpce + b);    // broadcast

    // ---- span search: indicator t[i] <= x < t[i+1], i in [0, 66] ----
    bool c1 = (__ldg(kt + lane)      <= x) & (x < __ldg(kt + lane + 1));
    bool c2 = (__ldg(kt + lane + 32) <= x) & (x < __ldg(kt + lane + 33));
    bool c3 = (lane < 3) && (__ldg(kt + lane + 64) <= x) && (x < __ldg(kt + lane + 65));
    unsigned m1 = __ballot_sync(0xffffffffu, c1);
    unsigned m2 = __ballot_sync(0xffffffffu, c2);
    unsigned m3 = __ballot_sync(0xffffffffu, c3);
    const int j = m1 ? (__ffs(m1) - 1)
                : m2 ? (31 + __ffs(m2))
                : m3 ? (63 + __ffs(m3))
                : -1;

    // ---- issue coefficient loads NOW (addresses depend only on j) ----
    const int jc = (j < 0) ? 3 : j;                 // weights are 0 when j<0
    const int n0 = min(max(jc - 3, 0), NCOEF - 1);
    const int n1 = min(max(jc - 2, 0), NCOEF - 1);
    const int n2 = min(max(jc - 1, 0), NCOEF - 1);
    const int n3 = min(max(jc,     0), NCOEF - 1);

    const float4* cr = (const float4*)(coef + (long long)b * (NCOEF * NCH));
    const int c4 = half * 32 + lane;                // float4 index within a 64-float4 row

    float4 r0 = __ldg(cr + n0 * 64 + c4);
    float4 r1 = __ldg(cr + n1 * 64 + c4);
    float4 r2 = __ldg(cr + n2 * 64 + c4);
    float4 r3 = __ldg(cr + n3 * 64 + c4);

    // ---- weights (runs under the coef-load latency; knot reloads hit L1) ----
    float w0 = 0.f, w1 = 0.f, w2 = 0.f, w3 = 0.f;
    if (j >= 0) {
        float tv[8];
        #pragma unroll
        for (int m = 0; m < 8; m++) {
            int i = j - 3 + m;
            tv[m] = __ldg(kt + min(max(i, 0), NT - 1));
        }
        #define TV(i) tv[(i) - (j - 3)]

        // degree 1: nonzero only at i in {j-1, j}; window i = j-2..j+1
        float B1[4];
        #pragma unroll
        for (int q = 0; q < 4; q++) {
            int i = j - 2 + q;
            float v = 0.f;
            if (i >= 0 && i <= NT - 3) {
                if (i == j)     v += gdiv(x - TV(i),     TV(i + 1) - TV(i));
                if (i + 1 == j) v += gdiv(TV(i + 2) - x, TV(i + 2) - TV(i + 1));
            }
            B1[q] = v;
        }
        // degree 2: window i = j-3..j+1
        float B2[5];
        #pragma unroll
        for (int q = 0; q < 5; q++) {
            int i = j - 3 + q;
            float v = 0.f;
            if (i >= 0 && i <= NT - 4) {
                float a1 = gdiv(x - TV(i),     TV(i + 2) - TV(i));
                float a2 = gdiv(TV(i + 3) - x, TV(i + 3) - TV(i + 1));
                float u1 = (q >= 1) ? B1[q - 1] : 0.f;
                float u2 = (q <= 3) ? B1[q]     : 0.f;
                v = a1 * u1 + a2 * u2;
            }
            B2[q] = v;
        }
        // degree 3: n = j-3..j
        float wq[4];
        #pragma unroll
        for (int q = 0; q < 4; q++) {
            int n = j - 3 + q;
            float v = 0.f;
            if (n >= 0 && n <= NT - 5) {
                float a1 = gdiv(x - TV(n),     TV(n + 3) - TV(n));
                float a2 = gdiv(TV(n + 4) - x, TV(n + 4) - TV(n + 1));
                v = a1 * B2[q] + a2 * B2[q + 1];
            }
            wq[q] = v;
        }
        w0 = wq[0]; w1 = wq[1]; w2 = wq[2]; w3 = wq[3];
        #undef TV
    }

    // ---- combine and store ----
    float4 a;
    a.x = w0 * r0.x + w1 * r1.x + w2 * r2.x + w3 * r3.x;
    a.y = w0 * r0.y + w1 * r1.y + w2 * r2.y + w3 * r3.y;
    a.z = w0 * r0.z + w1 * r1.z + w2 * r2.z + w3 * r3.z;
    a.w = w0 * r0.w + w1 * r1.w + w2 * r2.w + w3 * r3.w;

    ((float4*)(out + (long long)b * NCH))[c4] = a;
}

extern "C" void kernel_launch(void* const* d_in, const int* in_sizes, int n_in,
                              void* d_out, int out_size) {
    const float* coef  = (const float*)d_in[0];  // [4096, 64, 256]
    const float* knots = (const float*)d_in[1];  // [4096, 68]
    const float* inpce = (const float*)d_in[2];  // [4096, 1]
    float* out = (float*)d_out;                  // [4096, 256]

    bspline_kernel<<<NB / ROWS_PER_BLOCK, WARPS_PER_BLOCK * 32>>>(coef, knots, inpce, out);
}

// round 5
// speedup vs baseline: 1.1667x; 1.1667x over previous
#include <cuda_runtime.h>
#include <cuda_bf16.h>

// BSplineNN: out[b,c] = sum_n coef[b,n,c] * B_{n,3}(x_b)
// B=4096, n=64, C=256, K=3, T=68.  One WARP per batch row.
// Span j via ballots -> issue 8x LDG.128 coef loads immediately ->
// compute the 4 nonzero cubic weights while loads are in flight.
// Interior spans (3<=j<=63): closed-form, 6 reciprocals, NO guards
// (every denominator contains [t[j], t[j+1]] which is strictly positive).
// Edge spans: fully-guarded reference recurrence (warp-uniform branch).

#define NB    4096
#define NCOEF 64
#define NCH   256
#define NT    68
#define WARPS_PER_BLOCK 4

__device__ __forceinline__ float gdiv(float a, float d) {
    return (d == 0.0f) ? 0.0f : __fdividef(a, d);
}

__global__ __launch_bounds__(WARPS_PER_BLOCK * 32)
void bspline_kernel(const float* __restrict__ coef,   // [B, 64, 256]
                    const float* __restrict__ knots,  // [B, 68]
                    const float* __restrict__ inpce,  // [B, 1]
                    float* __restrict__ out)          // [B, 256]
{
    const int lane = threadIdx.x & 31;
    const int b    = blockIdx.x * WARPS_PER_BLOCK + (threadIdx.x >> 5);

    const float* kt = knots + b * NT;
    const float  x  = __ldg(inpce + b);    // broadcast

    // ---- span search: indicator t[i] <= x < t[i+1], i in [0, 66] ----
    bool c1 = (__ldg(kt + lane)      <= x) & (x < __ldg(kt + lane + 1));
    bool c2 = (__ldg(kt + lane + 32) <= x) & (x < __ldg(kt + lane + 33));
    bool c3 = (lane < 3) && (__ldg(kt + lane + 64) <= x) && (x < __ldg(kt + lane + 65));
    unsigned m1 = __ballot_sync(0xffffffffu, c1);
    unsigned m2 = __ballot_sync(0xffffffffu, c2);
    unsigned m3 = __ballot_sync(0xffffffffu, c3);
    const int j = m1 ? (__ffs(m1) - 1)
                : m2 ? (31 + __ffs(m2))
                : m3 ? (63 + __ffs(m3))
                : -1;

    // ---- issue coefficient loads NOW (addresses depend only on j) ----
    const int jc = (j < 0) ? 3 : j;
    const int n0 = min(max(jc - 3, 0), NCOEF - 1);
    const int n1 = min(max(jc - 2, 0), NCOEF - 1);
    const int n2 = min(max(jc - 1, 0), NCOEF - 1);
    const int n3 = min(max(jc,     0), NCOEF - 1);

    const float4* cr = (const float4*)(coef + (long long)b * (NCOEF * NCH));
    float4 r00 = __ldg(cr + n0 * 64 + lane);
    float4 r01 = __ldg(cr + n0 * 64 + lane + 32);
    float4 r10 = __ldg(cr + n1 * 64 + lane);
    float4 r11 = __ldg(cr + n1 * 64 + lane + 32);
    float4 r20 = __ldg(cr + n2 * 64 + lane);
    float4 r21 = __ldg(cr + n2 * 64 + lane + 32);
    float4 r30 = __ldg(cr + n3 * 64 + lane);
    float4 r31 = __ldg(cr + n3 * 64 + lane + 32);

    // ---- weights (runs under coef-load latency; knot reloads hit L1) ----
    float w0, w1, w2, w3;
    if (j >= 3 && j <= NCOEF - 1) {
        // Interior fast path. Knots used: t[j-2 .. j+3].
        // All denominators contain [t[j], t[j+1]] and t[j] <= x < t[j+1]
        // implies t[j+1] - t[j] > 0, so every denominator is > 0: no guards.
        float t0 = __ldg(kt + j - 2);
        float t1 = __ldg(kt + j - 1);
        float t2 = __ldg(kt + j);
        float t3 = __ldg(kt + j + 1);
        float t4 = __ldg(kt + j + 2);
        float t5 = __ldg(kt + j + 3);

        float i1  = __fdividef(1.0f, t3 - t2);  // deg-1 shared denom
        float b1m = (t3 - x) * i1;              // b1[j-1]
        float b1c = (x - t2) * i1;              // b1[j]

        float i20 = __fdividef(1.0f, t3 - t1);
        float i21 = __fdividef(1.0f, t4 - t2);
        float b2a = (t3 - x) * i20 * b1m;                          // b2[j-2]
        float b2b = (x - t1) * i20 * b1m + (t4 - x) * i21 * b1c;   // b2[j-1]
        float b2c = (x - t2) * i21 * b1c;                          // b2[j]

        float i30 = __fdividef(1.0f, t3 - t0);
        float i31 = __fdividef(1.0f, t4 - t1);
        float i32 = __fdividef(1.0f, t5 - t2);
        w0 = (t3 - x) * i30 * b2a;                                 // b3[j-3]
        w1 = (x - t0) * i30 * b2a + (t4 - x) * i31 * b2b;          // b3[j-2]
        w2 = (x - t1) * i31 * b2b + (t5 - x) * i32 * b2c;          // b3[j-1]
        w3 = (x - t2) * i32 * b2c;                                 // b3[j]
    } else {
        // Edge / out-of-range path: fully guarded reference recurrence.
        w0 = w1 = w2 = w3 = 0.f;
        if (j >= 0) {
            float tv[8];
            #pragma unroll
            for (int m = 0; m < 8; m++) {
                int i = j - 3 + m;
                tv[m] = __ldg(kt + min(max(i, 0), NT - 1));
            }
            #define TV(i) tv[(i) - (j - 3)]
            float B1[4];
            #pragma unroll
            for (int q = 0; q < 4; q++) {
                int i = j - 2 + q;
                float v = 0.f;
                if (i >= 0 && i <= NT - 3) {
                    if (i == j)     v += gdiv(x - TV(i),     TV(i + 1) - TV(i));
                    if (i + 1 == j) v += gdiv(TV(i + 2) - x, TV(i + 2) - TV(i + 1));
                }
                B1[q] = v;
            }
            float B2[5];
            #pragma unroll
            for (int q = 0; q < 5; q++) {
                int i = j - 3 + q;
                float v = 0.f;
                if (i >= 0 && i <= NT - 4) {
                    float a1 = gdiv(x - TV(i),     TV(i + 2) - TV(i));
                    float a2 = gdiv(TV(i + 3) - x, TV(i + 3) - TV(i + 1));
                    float u1 = (q >= 1) ? B1[q - 1] : 0.f;
                    float u2 = (q <= 3) ? B1[q]     : 0.f;
                    v = a1 * u1 + a2 * u2;
                }
                B2[q] = v;
            }
            float wq[4];
            #pragma unroll
            for (int q = 0; q < 4; q++) {
                int n = j - 3 + q;
                float v = 0.f;
                if (n >= 0 && n <= NT - 5) {
                    float a1 = gdiv(x - TV(n),     TV(n + 3) - TV(n));
                    float a2 = gdiv(TV(n + 4) - x, TV(n + 4) - TV(n + 1));
                    v = a1 * B2[q] + a2 * B2[q + 1];
                }
                wq[q] = v;
            }
            w0 = wq[0]; w1 = wq[1]; w2 = wq[2]; w3 = wq[3];
            #undef TV
        }
    }

    // ---- combine and store (256 channels per warp) ----
    float4 a0, a1;
    a0.x = w0 * r00.x + w1 * r10.x + w2 * r20.x + w3 * r30.x;
    a0.y = w0 * r00.y + w1 * r10.y + w2 * r20.y + w3 * r30.y;
    a0.z = w0 * r00.z + w1 * r10.z + w2 * r20.z + w3 * r30.z;
    a0.w = w0 * r00.w + w1 * r10.w + w2 * r20.w + w3 * r30.w;
    a1.x = w0 * r01.x + w1 * r11.x + w2 * r21.x + w3 * r31.x;
    a1.y = w0 * r01.y + w1 * r11.y + w2 * r21.y + w3 * r31.y;
    a1.z = w0 * r01.z + w1 * r11.z + w2 * r21.z + w3 * r31.z;
    a1.w = w0 * r01.w + w1 * r11.w + w2 * r21.w + w3 * r31.w;

    float4* o = (float4*)(out + (long long)b * NCH);
    o[lane]      = a0;
    o[lane + 32] = a1;
}

extern "C" void kernel_launch(void* const* d_in, const int* in_sizes, int n_in,
                              void* d_out, int out_size) {
    const float* coef  = (const float*)d_in[0];  // [4096, 64, 256]
    const float* knots = (const float*)d_in[1];  // [4096, 68]
    const float* inpce = (const float*)d_in[2];  // [4096, 1]
    float* out = (float*)d_out;                  // [4096, 256]

    bspline_kernel<<<NB / WARPS_PER_BLOCK, WARPS_PER_BLOCK * 32>>>(coef, knots, inpce, out);
}